// round 2
// baseline (speedup 1.0000x reference)
#include <cuda_runtime.h>
#include <stdint.h>

// Problem constants
#define Bc 32
#define Nc 512
#define Gc 64
#define Tc 16
#define Dc 256
static __device__ __constant__ float NEGV = -1.0e10f;

// Scratch: V[g][d] = sum_f W[d][f] * goal_type[g][f]   (2048 x 256 floats = 2MB)
__device__ float g_V[Bc * Gc * Dc];
// tree_mask dtype sniffer result: 0 = u8 bytes, 1 = int32, 2 = float32
__device__ int g_mask_kind;

// ---------------------------------------------------------------------------
// Kernel 0: classify tree_mask storage. Only the first 16384 bytes (= 4096
// words) are guaranteed in-bounds for all candidate dtypes, and that is
// enough: u8-packed bools (p=0.7 true) virtually always produce words with
// high bytes set; int32 bools are all {0,1}; f32 bools are {0, 0x3F800000}.
// ---------------------------------------------------------------------------
__global__ void detect_mask_kind_kernel(const uint32_t* __restrict__ mw) {
    __shared__ int ok_i32, ok_f32;
    if (threadIdx.x == 0) { ok_i32 = 1; ok_f32 = 1; }
    __syncthreads();
    int li = 1, lf = 1;
    for (int i = threadIdx.x; i < 4096; i += blockDim.x) {
        uint32_t w = mw[i];
        if (!(w == 0u || w == 1u)) li = 0;
        if (!(w == 0u || w == 0x3F800000u)) lf = 0;
    }
    if (!li) ok_i32 = 0;   // benign race: all writers store 0
    if (!lf) ok_f32 = 0;
    __syncthreads();
    if (threadIdx.x == 0) g_mask_kind = ok_i32 ? 1 : (ok_f32 ? 2 : 0);
}

// ---------------------------------------------------------------------------
// Kernel 1: V[g][d] = sum_f W[d][f] * goal_type[g][f]
// goal_type[g] is row 0 of token dim: goal + g*Tc*Dc.
// Block = 256 threads (thread d owns column d), handles 32 g's.
// goal rows staged in smem (broadcast reads), W streamed per-thread.
// ---------------------------------------------------------------------------
__global__ void compute_V_kernel(const float* __restrict__ goal,
                                 const float* __restrict__ W) {
    __shared__ float sg[32][Dc];           // 32 KB
    const int g0 = blockIdx.x * 32;
    for (int i = threadIdx.x; i < 32 * Dc; i += blockDim.x) {
        int g = i >> 8, f = i & 255;
        sg[g][f] = goal[(size_t)(g0 + g) * (Tc * Dc) + f];
    }
    __syncthreads();
    const int d = threadIdx.x;
    float acc[32];
#pragma unroll
    for (int g = 0; g < 32; g++) acc[g] = 0.f;
    const float4* Wrow = reinterpret_cast<const float4*>(W + (size_t)d * Dc);
#pragma unroll 4
    for (int f4 = 0; f4 < Dc / 4; f4++) {
        float4 w = Wrow[f4];
#pragma unroll
        for (int g = 0; g < 32; g++) {
            float4 s = reinterpret_cast<const float4*>(sg[g])[f4];  // broadcast
            acc[g] += w.x * s.x + w.y * s.y + w.z * s.z + w.w * s.w;
        }
    }
#pragma unroll
    for (int g = 0; g < 32; g++)
        g_V[(size_t)(g0 + g) * Dc + d] = acc[g];
}

// ---------------------------------------------------------------------------
// Kernel 2: lemma_preds[e] = dot(scope_type[src[e]], V[tgt[e]]) + bias.
// One warp per edge; 2x float4 per lane per operand (fully coalesced 128B
// lines), shfl-tree reduce. L2-resident working set (16MB + 2MB).
// ---------------------------------------------------------------------------
__global__ void edge_kernel(const float* __restrict__ scope,
                            const int* __restrict__ ei,
                            const float* __restrict__ bias,
                            float* __restrict__ out, int E) {
    const int e = blockIdx.x * (blockDim.x >> 5) + (threadIdx.x >> 5);
    if (e >= E) return;
    const int lane = threadIdx.x & 31;
    const int src = ei[e];
    const int tgt = ei[E + e];
    const float4* s = reinterpret_cast<const float4*>(scope + (size_t)src * (Tc * Dc));
    const float4* v = reinterpret_cast<const float4*>(g_V + (size_t)tgt * Dc);
    float4 s0 = s[lane], s1 = s[lane + 32];
    float4 v0 = v[lane], v1 = v[lane + 32];
    float p = s0.x * v0.x + s0.y * v0.y + s0.z * v0.z + s0.w * v0.w
            + s1.x * v1.x + s1.y * v1.y + s1.z * v1.z + s1.w * v1.w;
#pragma unroll
    for (int o = 16; o; o >>= 1) p += __shfl_xor_sync(0xffffffffu, p, o);
    if (lane == 0) out[e] = p + __ldg(bias);
}

// ---------------------------------------------------------------------------
// Kernel 3: lm_preds[m][n] = dot(mask_reprs[m], scope_type[batch_pts[m]][n]),
// masked by tree_mask[batch_pts[m]][n] -> NEG.
// Grid = (16 n-tiles, 32 batches). Each block gathers the m-list for its
// batch (avg 32 of 1024), holds 32 scope-type rows in registers
// (warp w owns 4 rows), and streams mask rows through smem.
// ---------------------------------------------------------------------------
__global__ void lm_kernel(const float* __restrict__ scope,
                          const int* __restrict__ lm_idx,
                          const int* __restrict__ batch_pts,
                          const void* __restrict__ tree_mask,
                          float* __restrict__ out, int M) {
    __shared__ float s_mask[Dc];
    __shared__ int s_list[1024];
    __shared__ int s_cnt;
    __shared__ unsigned s_tm;
    const int b = blockIdx.y;
    const int n0 = blockIdx.x * 32;
    const int tid = threadIdx.x, lane = tid & 31, w = tid >> 5;

    if (tid == 0) s_cnt = 0;
    __syncthreads();
    for (int m = tid; m < M; m += blockDim.x)
        if (batch_pts[m] == b) { int p = atomicAdd(&s_cnt, 1); s_list[p] = m; }

    if (w == 0) {
        const int n = n0 + lane;
        const int kind = g_mask_kind;
        bool mk;
        if (kind == 0)      mk = ((const uint8_t*)tree_mask)[b * Nc + n] != 0;
        else if (kind == 1) mk = ((const int*)tree_mask)[b * Nc + n] != 0;
        else                mk = ((const float*)tree_mask)[b * Nc + n] != 0.f;
        unsigned bal = __ballot_sync(0xffffffffu, mk);
        if (lane == 0) s_tm = bal;
    }

    // Warp w owns n rows [n0 + 4w, n0 + 4w + 3], held in registers.
    float4 sr[4][2];
#pragma unroll
    for (int j = 0; j < 4; j++) {
        const int n = n0 + w * 4 + j;
        const float4* row =
            reinterpret_cast<const float4*>(scope + (size_t)(b * Nc + n) * (Tc * Dc));
        sr[j][0] = row[lane];
        sr[j][1] = row[lane + 32];
    }
    __syncthreads();
    const int cnt = s_cnt;
    const unsigned tmbits = s_tm;

    for (int i = 0; i < cnt; i++) {
        const int m = s_list[i];
        s_mask[tid] = scope[(size_t)lm_idx[m] * Dc + tid];   // 256 threads = Dc
        __syncthreads();
        float4 m0 = reinterpret_cast<const float4*>(s_mask)[lane];
        float4 m1 = reinterpret_cast<const float4*>(s_mask)[lane + 32];
#pragma unroll
        for (int j = 0; j < 4; j++) {
            float p = sr[j][0].x * m0.x + sr[j][0].y * m0.y
                    + sr[j][0].z * m0.z + sr[j][0].w * m0.w
                    + sr[j][1].x * m1.x + sr[j][1].y * m1.y
                    + sr[j][1].z * m1.z + sr[j][1].w * m1.w;
#pragma unroll
            for (int o = 16; o; o >>= 1) p += __shfl_xor_sync(0xffffffffu, p, o);
            if (lane == 0) {
                const int n = n0 + w * 4 + j;
                out[(size_t)m * Nc + n] = ((tmbits >> (n - n0)) & 1u) ? p : NEGV;
            }
        }
        __syncthreads();
    }
}

// ---------------------------------------------------------------------------
// Launcher. Input order (metadata): scope_token_reprs, goal_token_reprs, W,
// bias, edge_index, lm_mask_idx, batch_pts, tree_mask.
// Output: [lemma_preds (E) | lm_preds (M*Nc)] float32.
// ---------------------------------------------------------------------------
extern "C" void kernel_launch(void* const* d_in, const int* in_sizes, int n_in,
                              void* d_out, int out_size) {
    const float* scope = (const float*)d_in[0];
    const float* goal  = (const float*)d_in[1];
    const float* W     = (const float*)d_in[2];
    const float* bias  = (const float*)d_in[3];
    const int*   ei    = (const int*)d_in[4];
    const int*   lmidx = (const int*)d_in[5];
    const int*   bpts  = (const int*)d_in[6];
    const void*  tmask = d_in[7];
    float* out = (float*)d_out;

    const int E = in_sizes[4] / 2;   // edge_index is (2, E)
    const int M = in_sizes[5];

    detect_mask_kind_kernel<<<1, 256>>>((const uint32_t*)tmask);
    compute_V_kernel<<<(Bc * Gc) / 32, 256>>>(goal, W);
    edge_kernel<<<(E + 7) / 8, 256>>>(scope, ei, bias, out, E);
    lm_kernel<<<dim3(Nc / 32, Bc), 256>>>(scope, lmidx, bpts, tmask,
                                          out + E, M);
}